// round 5
// baseline (speedup 1.0000x reference)
#include <cuda_runtime.h>
#include <cstdint>

#define BB 8
#define CC 64
#define OO 64
#define HH 96
#define WW 96
#define HW (HH*WW)          // 9216
#define K2 9
#define NOFF 18

typedef unsigned long long ull;
typedef ulonglong2 ull2;

#define PACKF2(d, lo, hi) asm("mov.b64 %0, {%1,%2};" : "=l"(d) : "f"(lo), "f"(hi))
#define UNPKF2(lo, hi, s) asm("mov.b64 {%0,%1}, %2;" : "=f"(lo), "=f"(hi) : "l"(s))
#define FMA2(d, a, b, c)  asm("fma.rn.f32x2 %0, %1, %2, %3;" : "=l"(d) : "l"(a), "l"(b), "l"(c))
#define BAR_SYNC(id)   asm volatile("bar.sync %0, 384;"   :: "r"(id) : "memory")
#define BAR_ARRIVE(id) asm volatile("bar.arrive %0, 384;" :: "r"(id) : "memory")

// ---------------- scratch ----------------------------------------------------
__device__ float g_xt[BB * HW * CC];          // x in NHWC (~18.9 MB)
__device__ float g_offs[BB * HW * NOFF];      // offsets, pixel-major (~5.3 MB)
__device__ float g_wt[K2 * CC * OO];          // conv_w as [k][c][o]
__device__ float g_owt[CC * K2 * 20];         // offset_w as [c][tap][j pad 20]

// ---------------- kernel T1: NCHW -> NHWC transpose -------------------------
__global__ void transpose_x_kernel(const float* __restrict__ x, float* __restrict__ xt) {
    __shared__ float tile[32][33];
    int blk = blockIdx.x;            // 8 * 2 * 288
    int pt  = blk % 288;
    int ct  = (blk / 288) & 1;
    int b   = blk / 576;
    int lx = threadIdx.x & 31, ly = threadIdx.x >> 5;
    int p0 = pt * 32, c0 = ct * 32;
    const float* xb = x + (size_t)(b * CC + c0) * HW + p0;
#pragma unroll
    for (int i = 0; i < 4; i++) {
        int cc = ly + 8 * i;
        tile[cc][lx] = xb[(size_t)cc * HW + lx];
    }
    __syncthreads();
    float* xo = xt + (size_t)(b * HW + p0) * CC + c0;
#pragma unroll
    for (int i = 0; i < 4; i++) {
        int pp = ly + 8 * i;
        xo[(size_t)pp * CC + lx] = tile[lx][pp];
    }
}

// ---------------- kernel T2: weight re-layouts -------------------------------
__global__ void build_weights_kernel(const float* __restrict__ cw,
                                     const float* __restrict__ ow,
                                     float* __restrict__ wt,
                                     float* __restrict__ owt) {
    int idx = blockIdx.x * 256 + threadIdx.x;
    if (idx < OO * CC * K2) {
        int o = idx / (CC * K2);
        int r = idx % (CC * K2);
        int c = r / K2;
        int k = r % K2;
        wt[(k * CC + c) * OO + o] = cw[idx];
    }
    if (idx < NOFF * CC * K2) {
        int j = idx / (CC * K2);
        int r = idx % (CC * K2);
        int c = r / K2;
        int k = r % K2;
        owt[(c * K2 + k) * 20 + j] = ow[idx];
    }
}

// ---------------- kernel 1: offset conv (f32x2), 1 px / thread --------------
__global__ void __launch_bounds__(256) offset_conv_kernel(
    const float* __restrict__ x, const float* __restrict__ owt,
    const float* __restrict__ ob, float* __restrict__ offs)
{
    __shared__ float ws[CC * K2 * 20];
    __shared__ float bs[NOFF];
    int tid = threadIdx.x;
    for (int i = tid; i < CC * K2 * 20; i += 256) ws[i] = owt[i];
    if (tid < NOFF) bs[tid] = ob[tid];
    __syncthreads();

    int flat = blockIdx.x * 256 + tid;
    int b = flat / HW, p = flat % HW;
    int h = p / WW, w = p % WW;
    const float* x0 = x + (size_t)b * CC * HW;

    ull a0[9];
#pragma unroll
    for (int j = 0; j < 9; j++) a0[j] = 0ull;

    int yy[3], xx[3]; bool vy[3], vx[3];
#pragma unroll
    for (int d = 0; d < 3; d++) {
        yy[d] = h + d - 1; vy[d] = (unsigned)yy[d] < (unsigned)HH;
        xx[d] = w + d - 1; vx[d] = (unsigned)xx[d] < (unsigned)WW;
    }

    for (int c = 0; c < CC; c++) {
        float xv0[9];
        const float* xc0 = x0 + (size_t)c * HW;
#pragma unroll
        for (int dy = 0; dy < 3; dy++)
#pragma unroll
            for (int dx = 0; dx < 3; dx++) {
                int i = dy * 3 + dx;
                bool v = vy[dy] && vx[dx];
                xv0[i] = v ? xc0[yy[dy] * WW + xx[dx]] : 0.f;
            }
#pragma unroll
        for (int i = 0; i < 9; i++) {
            const float* row = ws + (c * K2 + i) * 20;
            ull s0;
            PACKF2(s0, xv0[i], xv0[i]);
#pragma unroll
            for (int j = 0; j < 9; j++) {
                ull wv = *(const ull*)(row + 2 * j);
                FMA2(a0[j], s0, wv, a0[j]);
            }
        }
    }
    float* o0 = offs + (size_t)flat * NOFF;
#pragma unroll
    for (int j = 0; j < 9; j++) {
        float lo, hi;
        UNPKF2(lo, hi, a0[j]);
        *(float2*)(o0 + 2 * j) = make_float2(lo + bs[2 * j], hi + bs[2 * j + 1]);
    }
}

// ---------------- kernel 2: warp-specialized fused kernel -------------------
// 384 threads: tid 0..255 consumers (GEMM), tid 256..383 producers (gather).
// Tile 128 px x 64 out. Double-buffered samples + weights.
// Barriers: full[buf]=1+buf  (producers arrive, consumers sync)
//           empty[buf]=3+buf (consumers arrive, producers sync)
#define SAMP_ST 68
#define SAMP_SZ (128 * SAMP_ST)                      // 8704 floats
#define SMEM_FUSED ((2 * SAMP_SZ + 2 * 4096) * 4)    // 102400 B

__global__ void __launch_bounds__(384, 2) fused_deform_kernel(
    const float* __restrict__ xt, const float* __restrict__ offs,
    const float* __restrict__ wt, const float* __restrict__ cb,
    float* __restrict__ out)
{
    extern __shared__ float sm[];
    float* samp = sm;                    // 2 * 8704
    float* wsb  = sm + 2 * SAMP_SZ;      // 2 * 4096

    int tid = threadIdx.x;
    int b   = blockIdx.x / 72;
    int p0  = (blockIdx.x % 72) * 128;

    if (tid >= 256) {
        // ================= producers: 4 warps =================
        int pt   = tid - 256;
        int warp = pt >> 5;
        int lane = pt & 31;
        int c2   = 2 * lane;
        const float* xt_b   = xt   + (size_t)b * HW * CC;
        const float* offs_p = offs + ((size_t)(b * HW + p0)) * NOFF;

        for (int k = 0; k < 9; k++) {
            int buf = k & 1;
            if (k >= 2) BAR_SYNC(3 + buf);

            // stage this tap's 64x64 weights (16 KB)
            {
                const float4* wsrc = (const float4*)(wt + k * 4096);
                float4* wdst = (float4*)(wsb + buf * 4096);
#pragma unroll
                for (int r = 0; r < 8; r++) wdst[pt + 128 * r] = wsrc[pt + 128 * r];
            }
            // fill 128 px of samples (32 per warp)
            float* sb = samp + buf * SAMP_SZ;
            int kdy = k / 3 - 1, kdx = k % 3 - 1;
#pragma unroll 2
            for (int j = 0; j < 32; j++) {
                int px = 4 * j + warp;
                int p = p0 + px;
                int h = p / WW, w = p - h * WW;
                float2 od = *(const float2*)(offs_p + px * NOFF + 2 * k);
                float py  = (float)(h + kdy) + od.x;
                float pxf = (float)(w + kdx) + od.y;
                float fy = floorf(py), fx = floorf(pxf);
                int y0 = (int)fy, x0 = (int)fx;
                float wy = py - fy, wx = pxf - fx;
                bool vy0 = (unsigned)y0 < (unsigned)HH;
                bool vy1 = (unsigned)(y0 + 1) < (unsigned)HH;
                bool vx0 = (unsigned)x0 < (unsigned)WW;
                bool vx1 = (unsigned)(x0 + 1) < (unsigned)WW;
                const float* base = xt_b + ((ptrdiff_t)y0 * WW + x0) * CC + c2;
                float2 z = make_float2(0.f, 0.f);
                float2 g00 = (vy0 && vx0) ? *(const float2*)(base)              : z;
                float2 g01 = (vy0 && vx1) ? *(const float2*)(base + CC)         : z;
                float2 g10 = (vy1 && vx0) ? *(const float2*)(base + WW*CC)      : z;
                float2 g11 = (vy1 && vx1) ? *(const float2*)(base + WW*CC + CC) : z;
                float w00 = (1.f - wy) * (1.f - wx);
                float w01 = (1.f - wy) * wx;
                float w10 = wy * (1.f - wx);
                float w11 = wy * wx;
                float sx = g00.x * w00 + g01.x * w01 + g10.x * w10 + g11.x * w11;
                float sy = g00.y * w00 + g01.y * w01 + g10.y * w10 + g11.y * w11;
                *(float2*)(sb + px * SAMP_ST + c2) = make_float2(sx, sy);
            }
            BAR_ARRIVE(1 + buf);
        }
    } else {
        // ================= consumers: 8 warps =================
        int tx  = tid & 7;          // out group: o = tx*8 .. +7
        int ty  = tid >> 3;         // px block: px = ty*4 .. +3
        int txo = tx * 8;

        ull acc[4][4];
#pragma unroll
        for (int i = 0; i < 4; i++)
#pragma unroll
            for (int j = 0; j < 4; j++) acc[i][j] = 0ull;

        const float* sbase0 = samp + (ty * 4) * SAMP_ST;

        for (int k = 0; k < 9; k++) {
            int buf = k & 1;
            BAR_SYNC(1 + buf);
            const float* sb = sbase0 + buf * SAMP_SZ;
            const float* wb = wsb + buf * 4096;
#pragma unroll 2
            for (int cc = 0; cc < 64; cc += 4) {
                float4 sv[4];
#pragma unroll
                for (int i = 0; i < 4; i++)
                    sv[i] = *(const float4*)(sb + i * SAMP_ST + cc);
#pragma unroll
                for (int r = 0; r < 4; r++) {
                    ull2 wA = *(const ull2*)(wb + (cc + r) * 64 + txo);
                    ull2 wB = *(const ull2*)(wb + (cc + r) * 64 + txo + 4);
#pragma unroll
                    for (int i = 0; i < 4; i++) {
                        float s = (r == 0) ? sv[i].x : (r == 1) ? sv[i].y :
                                  (r == 2) ? sv[i].z : sv[i].w;
                        ull ss;
                        PACKF2(ss, s, s);
                        FMA2(acc[i][0], ss, wA.x, acc[i][0]);
                        FMA2(acc[i][1], ss, wA.y, acc[i][1]);
                        FMA2(acc[i][2], ss, wB.x, acc[i][2]);
                        FMA2(acc[i][3], ss, wB.y, acc[i][3]);
                    }
                }
            }
            BAR_ARRIVE(3 + buf);
        }

        // epilogue: px = p0 + ty*4 + i (contiguous 4), outs txo..txo+7
        int p = p0 + ty * 4;
#pragma unroll
        for (int j = 0; j < 4; j++) {
            float bL = cb[txo + 2 * j];
            float bH = cb[txo + 2 * j + 1];
            float4 vlo, vhi;
            float lo, hi;
            UNPKF2(lo, hi, acc[0][j]); vlo.x = lo + bL; vhi.x = hi + bH;
            UNPKF2(lo, hi, acc[1][j]); vlo.y = lo + bL; vhi.y = hi + bH;
            UNPKF2(lo, hi, acc[2][j]); vlo.z = lo + bL; vhi.z = hi + bH;
            UNPKF2(lo, hi, acc[3][j]); vlo.w = lo + bL; vhi.w = hi + bH;
            float* oL = out + (size_t)(b * OO + txo + 2 * j) * HW + p;
            *(float4*)oL = vlo;
            *(float4*)(oL + HW) = vhi;
        }
    }
}

// ---------------- launch ------------------------------------------------------
extern "C" void kernel_launch(void* const* d_in, const int* in_sizes, int n_in,
                              void* d_out, int out_size) {
    const float* x  = (const float*)d_in[0];
    const float* ow = (const float*)d_in[1];
    const float* ob = (const float*)d_in[2];
    const float* cw = (const float*)d_in[3];
    const float* cb = (const float*)d_in[4];
    float* out = (float*)d_out;

    float *xt, *offs, *wt, *owt;
    cudaGetSymbolAddress((void**)&xt,   g_xt);
    cudaGetSymbolAddress((void**)&offs, g_offs);
    cudaGetSymbolAddress((void**)&wt,   g_wt);
    cudaGetSymbolAddress((void**)&owt,  g_owt);

    cudaFuncSetAttribute(fused_deform_kernel,
                         cudaFuncAttributeMaxDynamicSharedMemorySize, SMEM_FUSED);

    transpose_x_kernel<<<4608, 256>>>(x, xt);
    build_weights_kernel<<<144, 256>>>(cw, ow, wt, owt);
    offset_conv_kernel<<<288, 256>>>(x, owt, ob, offs);
    fused_deform_kernel<<<576, 384, SMEM_FUSED>>>(xt, offs, wt, cb, out);
}